// round 2
// baseline (speedup 1.0000x reference)
#include <cuda_runtime.h>
#include <cuda_bf16.h>
#include <math.h>

// ---------------------------------------------------------------------------
// MLA attention pipeline, fp32 baseline.
// B=4, T=2048, D=512, H=8, KVH=2, HD=64, DN=32, DR=32
// ---------------------------------------------------------------------------

#define Bb   4
#define Tt   2048
#define Dd   512
#define Hh   8
#define KVHh 2
#define HDd  64
#define BT   (Bb*Tt)      // 8192
#define EPSF 1e-6f

// ------------------------- scratch (device globals) ------------------------
__device__ float g_cq  [BT*256];
__device__ float g_qn  [BT*256];
__device__ float g_qr  [BT*256];
__device__ float g_ckv [BT*128];
__device__ float g_kn  [BT*64];
__device__ float g_kr  [BT*64];
__device__ float g_vraw[BT*128];
__device__ float g_vres[BT*512];
__device__ float g_q   [BT*512];              // [B,H,T,HD]
__device__ float g_k   [Bb*KVHh*Tt*HDd];      // [B,KVH,T,HD]
__device__ float g_v   [Bb*KVHh*Tt*HDd];      // [B,KVH,T,HD]
__device__ float g_ao  [BT*512];              // attn_out + v_res, [B*T, H*HD]

// ---------------------------------------------------------------------------
// SGEMM 64x64 tile (for N%64 cases): C[M,N] = A[M,K] * B[K,N], row-major.
// Requires M%64==0, N%64==0, K%16==0.
// ---------------------------------------------------------------------------
__global__ __launch_bounds__(256) void sgemm64(
    const float* __restrict__ A, const float* __restrict__ B,
    float* __restrict__ C, int M, int N, int K)
{
    __shared__ float As[16][64];
    __shared__ float Bs[16][64];

    const int bm = blockIdx.y * 64;
    const int bn = blockIdx.x * 64;
    const int tid = threadIdx.x;
    const int ty = tid >> 4, tx = tid & 15;     // 16x16 threads
    const int am = tid >> 2, ak4 = tid & 3;     // A loader
    const int bk = tid >> 4, bn4 = tid & 15;    // B loader

    float acc[4][4] = {};

    for (int k0 = 0; k0 < K; k0 += 16) {
        float4 av = *(const float4*)(A + (size_t)(bm + am) * K + k0 + ak4 * 4);
        float4 bv = *(const float4*)(B + (size_t)(k0 + bk) * N + bn + bn4 * 4);
        __syncthreads();
        As[ak4 * 4 + 0][am] = av.x;
        As[ak4 * 4 + 1][am] = av.y;
        As[ak4 * 4 + 2][am] = av.z;
        As[ak4 * 4 + 3][am] = av.w;
        *(float4*)&Bs[bk][bn4 * 4] = bv;
        __syncthreads();
        #pragma unroll
        for (int kk = 0; kk < 16; ++kk) {
            float4 a = *(const float4*)&As[kk][ty * 4];
            float4 b = *(const float4*)&Bs[kk][tx * 4];
            acc[0][0] += a.x * b.x; acc[0][1] += a.x * b.y; acc[0][2] += a.x * b.z; acc[0][3] += a.x * b.w;
            acc[1][0] += a.y * b.x; acc[1][1] += a.y * b.y; acc[1][2] += a.y * b.z; acc[1][3] += a.y * b.w;
            acc[2][0] += a.z * b.x; acc[2][1] += a.z * b.y; acc[2][2] += a.z * b.z; acc[2][3] += a.z * b.w;
            acc[3][0] += a.w * b.x; acc[3][1] += a.w * b.y; acc[3][2] += a.w * b.z; acc[3][3] += a.w * b.w;
        }
    }

    #pragma unroll
    for (int i = 0; i < 4; ++i) {
        float4 o = make_float4(acc[i][0], acc[i][1], acc[i][2], acc[i][3]);
        *(float4*)(C + (size_t)(bm + ty * 4 + i) * N + bn + tx * 4) = o;
    }
}

// ---------------------------------------------------------------------------
// SGEMM 128x128 tile, BK=8, 256 threads, 2x2 blocks of 4x4 microtiles.
// 1 FFMA/byte of LDS (balanced). Requires M%128==0, N%128==0, K%8==0.
// Thread (ty,tx) owns rows {ty*4+i, 64+ty*4+i}, cols {tx*4+j, 64+tx*4+j}:
// the split-64 addressing keeps both LDS.128 streams conflict-free.
// ---------------------------------------------------------------------------
__global__ __launch_bounds__(256) void sgemm128(
    const float* __restrict__ A, const float* __restrict__ B,
    float* __restrict__ C, int M, int N, int K)
{
    __shared__ float As[8][128];
    __shared__ float Bs[8][128];

    const int bm = blockIdx.y * 128;
    const int bn = blockIdx.x * 128;
    const int tid = threadIdx.x;
    const int ty = tid >> 4, tx = tid & 15;        // 16x16 threads
    const int arow = tid >> 1, ak = (tid & 1) * 4; // A loader: 128 rows x 8 k
    const int bk = tid >> 5, bcol = (tid & 31) * 4;// B loader: 8 rows x 128 n

    float acc[2][2][4][4] = {};

    for (int k0 = 0; k0 < K; k0 += 8) {
        float4 av = *(const float4*)(A + (size_t)(bm + arow) * K + k0 + ak);
        float4 bv = *(const float4*)(B + (size_t)(k0 + bk) * N + bn + bcol);
        __syncthreads();
        As[ak + 0][arow] = av.x;
        As[ak + 1][arow] = av.y;
        As[ak + 2][arow] = av.z;
        As[ak + 3][arow] = av.w;
        *(float4*)&Bs[bk][bcol] = bv;
        __syncthreads();
        #pragma unroll
        for (int kk = 0; kk < 8; ++kk) {
            float4 a0 = *(const float4*)&As[kk][ty * 4];
            float4 a1 = *(const float4*)&As[kk][64 + ty * 4];
            float4 b0 = *(const float4*)&Bs[kk][tx * 4];
            float4 b1 = *(const float4*)&Bs[kk][64 + tx * 4];
            #pragma unroll
            for (int ri = 0; ri < 2; ++ri) {
                float4 a = ri ? a1 : a0;
                #pragma unroll
                for (int ci = 0; ci < 2; ++ci) {
                    float4 b = ci ? b1 : b0;
                    acc[ri][ci][0][0] += a.x * b.x; acc[ri][ci][0][1] += a.x * b.y;
                    acc[ri][ci][0][2] += a.x * b.z; acc[ri][ci][0][3] += a.x * b.w;
                    acc[ri][ci][1][0] += a.y * b.x; acc[ri][ci][1][1] += a.y * b.y;
                    acc[ri][ci][1][2] += a.y * b.z; acc[ri][ci][1][3] += a.y * b.w;
                    acc[ri][ci][2][0] += a.z * b.x; acc[ri][ci][2][1] += a.z * b.y;
                    acc[ri][ci][2][2] += a.z * b.z; acc[ri][ci][2][3] += a.z * b.w;
                    acc[ri][ci][3][0] += a.w * b.x; acc[ri][ci][3][1] += a.w * b.y;
                    acc[ri][ci][3][2] += a.w * b.z; acc[ri][ci][3][3] += a.w * b.w;
                }
            }
        }
    }

    #pragma unroll
    for (int ri = 0; ri < 2; ++ri)
        #pragma unroll
        for (int i = 0; i < 4; ++i) {
            size_t row = (size_t)(bm + ri * 64 + ty * 4 + i);
            #pragma unroll
            for (int ci = 0; ci < 2; ++ci) {
                float4 o = make_float4(acc[ri][ci][i][0], acc[ri][ci][i][1],
                                       acc[ri][ci][i][2], acc[ri][ci][i][3]);
                *(float4*)(C + row * N + bn + ci * 64 + tx * 4) = o;
            }
        }
}

// ---------------------------------------------------------------------------
// In-place RMSNorm over rows of length `dim` (128 or 256). 1 block per row.
// ---------------------------------------------------------------------------
__global__ __launch_bounds__(128) void rms_inplace(
    float* __restrict__ x, const float* __restrict__ w, int dim)
{
    const int row = blockIdx.x;
    float* xr = x + (size_t)row * dim;
    float ss = 0.f;
    for (int i = threadIdx.x; i < dim; i += 128) { float v = xr[i]; ss += v * v; }
    #pragma unroll
    for (int off = 16; off; off >>= 1) ss += __shfl_xor_sync(0xffffffffu, ss, off);
    __shared__ float sred[4];
    if ((threadIdx.x & 31) == 0) sred[threadIdx.x >> 5] = ss;
    __syncthreads();
    float tot = sred[0] + sred[1] + sred[2] + sred[3];
    float rr = rsqrtf(tot / (float)dim + EPSF);
    for (int i = threadIdx.x; i < dim; i += 128) xr[i] = xr[i] * rr * w[i];
}

// ---------------------------------------------------------------------------
// Assemble: RoPE(q_rope,k_rope) + concat + per-head RMSNorm + layout change
// to [B,h,T,64]; also reshapes V. One block per (t,b), 256 threads.
// ---------------------------------------------------------------------------
__global__ __launch_bounds__(256) void assemble(
    const float* __restrict__ qn, const float* __restrict__ qr,
    const float* __restrict__ kn, const float* __restrict__ kr,
    const float* __restrict__ vraw,
    const float* __restrict__ qhw, const float* __restrict__ khw,
    float* __restrict__ q, float* __restrict__ k, float* __restrict__ v)
{
    const int t = blockIdx.x, b = blockIdx.y;
    const int row = b * Tt + t;
    const int w = threadIdx.x >> 5, lane = threadIdx.x & 31;

    // inv_freq = 500000^(-fi/16); fp64 exp/log then cast, then fp32 phase +
    // sincos, matching the numpy fp32 table construction to ~1 ulp.
    const int fi = lane & 15;
    float invf = (float)exp(-((double)fi / 16.0) * log(500000.0));
    float ph = (float)t * invf;
    float sv, cv;
    sincosf(ph, &sv, &cv);   // sv = sin, cv = cos

    // ---- Q heads: warp w handles head h = w ----
    {
        const int h = w;
        const float* qnr = qn + (size_t)row * 256 + h * 32;
        const float* qrr = qr + (size_t)row * 256 + h * 32;
        float v0 = qnr[lane];
        float x1 = qrr[lane];
        float xr_ = (lane < 16) ? -qrr[lane + 16] : qrr[lane - 16];
        float v1 = x1 * cv + xr_ * sv;
        float ss = v0 * v0 + v1 * v1;
        #pragma unroll
        for (int off = 16; off; off >>= 1) ss += __shfl_xor_sync(0xffffffffu, ss, off);
        float rr = rsqrtf(ss / 64.0f + EPSF);
        float* qo = q + ((size_t)(b * Hh + h) * Tt + t) * 64;
        qo[lane]      = v0 * rr * qhw[lane];
        qo[lane + 32] = v1 * rr * qhw[lane + 32];
    }

    // ---- K heads: warps 0,1 handle kv head w ----
    if (w < KVHh) {
        const int kvh = w;
        const float* knr = kn + (size_t)row * 64 + kvh * 32;
        const float* krr = kr + (size_t)row * 64 + kvh * 32;
        float v0 = knr[lane];
        float x1 = krr[lane];
        float xr_ = (lane < 16) ? -krr[lane + 16] : krr[lane - 16];
        float v1 = x1 * cv + xr_ * sv;
        float ss = v0 * v0 + v1 * v1;
        #pragma unroll
        for (int off = 16; off; off >>= 1) ss += __shfl_xor_sync(0xffffffffu, ss, off);
        float rr = rsqrtf(ss / 64.0f + EPSF);
        float* ko = k + ((size_t)(b * KVHh + kvh) * Tt + t) * 64;
        ko[lane]      = v0 * rr * khw[lane];
        ko[lane + 32] = v1 * rr * khw[lane + 32];
    }

    // ---- V reshape: [B*T, KVH*64] -> [B,KVH,T,64] ----
    for (int i = threadIdx.x; i < 128; i += 256) {
        int kvh = i >> 6, d = i & 63;
        v[((size_t)(b * KVHh + kvh) * Tt + t) * 64 + d] = vraw[(size_t)row * 128 + i];
    }
}

// ---------------------------------------------------------------------------
// Fused causal flash attention, fp32. Grid (T/64, H, B), 256 threads.
// Qs / K-tile / P-tile stored transposed with an XOR float4-chunk swizzle so
// both inner GEMMs do conflict-free, aligned LDS.128 reads.
// out = softmax(QK^T * 0.125, causal) @ V + v_res
// ---------------------------------------------------------------------------
__device__ __forceinline__ int swz(int maj, int mnr) {
    return (maj << 6) + ((((mnr >> 2) ^ (maj & 15)) << 2) | (mnr & 3));
}

__global__ __launch_bounds__(256) void flash64(
    const float* __restrict__ Q, const float* __restrict__ Kk,
    const float* __restrict__ V, const float* __restrict__ vres,
    float* __restrict__ out)
{
    __shared__ float Qs[4096];   // [d][m], swizzled
    __shared__ float KPs[4096];  // K: [d][n] swizzled; reused as P: [k][m] swizzled
    __shared__ float Vs[4096];   // [k][d], natural

    const int qt = blockIdx.x, h = blockIdx.y, b = blockIdx.z;
    const int kvh = h >> 2;   // H/KVH = 4
    const float* qb = Q  + (((size_t)b * Hh   + h)   * Tt + qt * 64) * 64;
    const float* kb = Kk + (((size_t)b * KVHh + kvh) * Tt) * 64;
    const float* vb = V  + (((size_t)b * KVHh + kvh) * Tt) * 64;

    const int tid = threadIdx.x;
    const int r = tid >> 4, c = tid & 15;
    const int m0 = r * 4, n0 = c * 4;

    // load Q tile (pre-scaled by HD^-0.5), transposed+swizzled
    #pragma unroll
    for (int j = 0; j < 4; ++j) {
        int job = tid + j * 256;
        int row = job >> 4, d4 = job & 15, dd = d4 * 4;
        float4 val = *(const float4*)(qb + row * 64 + d4 * 4);
        Qs[swz(dd + 0, row)] = val.x * 0.125f;
        Qs[swz(dd + 1, row)] = val.y * 0.125f;
        Qs[swz(dd + 2, row)] = val.z * 0.125f;
        Qs[swz(dd + 3, row)] = val.w * 0.125f;
    }

    float O[4][4] = {};
    float mI[4] = {-3.0e38f, -3.0e38f, -3.0e38f, -3.0e38f};
    float lI[4] = {};

    for (int kt = 0; kt <= qt; ++kt) {
        const float* ktb = kb + (size_t)kt * 64 * 64;
        const float* vtb = vb + (size_t)kt * 64 * 64;
        __syncthreads();   // prev PV reads of KPs/Vs complete
        #pragma unroll
        for (int j = 0; j < 4; ++j) {
            int job = tid + j * 256;
            int row = job >> 4, d4 = job & 15, dd = d4 * 4;
            float4 kv4 = *(const float4*)(ktb + row * 64 + d4 * 4);
            KPs[swz(dd + 0, row)] = kv4.x;
            KPs[swz(dd + 1, row)] = kv4.y;
            KPs[swz(dd + 2, row)] = kv4.z;
            KPs[swz(dd + 3, row)] = kv4.w;
            *(float4*)&Vs[row * 64 + d4 * 4] = *(const float4*)(vtb + row * 64 + d4 * 4);
        }
        __syncthreads();

        // S = Q K^T (64x64x64)
        float S[4][4] = {};
        #pragma unroll 16
        for (int d = 0; d < 64; ++d) {
            float4 a  = *(const float4*)&Qs [swz(d, m0)];
            float4 bq = *(const float4*)&KPs[swz(d, n0)];
            S[0][0] += a.x * bq.x; S[0][1] += a.x * bq.y; S[0][2] += a.x * bq.z; S[0][3] += a.x * bq.w;
            S[1][0] += a.y * bq.x; S[1][1] += a.y * bq.y; S[1][2] += a.y * bq.z; S[1][3] += a.y * bq.w;
            S[2][0] += a.z * bq.x; S[2][1] += a.z * bq.y; S[2][2] += a.z * bq.z; S[2][3] += a.z * bq.w;
            S[3][0] += a.w * bq.x; S[3][1] += a.w * bq.y; S[3][2] += a.w * bq.z; S[3][3] += a.w * bq.w;
        }

        if (kt == qt) {
            #pragma unroll
            for (int i = 0; i < 4; ++i)
                #pragma unroll
                for (int j = 0; j < 4; ++j)
                    if (n0 + j > m0 + i) S[i][j] = -1e30f;
        }

        // online softmax (row stats across the 16 lanes of a row group)
        #pragma unroll
        for (int i = 0; i < 4; ++i) {
            float mt = fmaxf(fmaxf(S[i][0], S[i][1]), fmaxf(S[i][2], S[i][3]));
            #pragma unroll
            for (int off = 8; off; off >>= 1)
                mt = fmaxf(mt, __shfl_xor_sync(0xffffffffu, mt, off, 16));
            float mn = fmaxf(mI[i], mt);
            float alpha = __expf(mI[i] - mn);
            mI[i] = mn;
            float sum = 0.f;
            #pragma unroll
            for (int j = 0; j < 4; ++j) { S[i][j] = __expf(S[i][j] - mn); sum += S[i][j]; }
            #pragma unroll
            for (int off = 8; off; off >>= 1)
                sum += __shfl_xor_sync(0xffffffffu, sum, off, 16);
            lI[i] = lI[i] * alpha + sum;
            #pragma unroll
            for (int j = 0; j < 4; ++j) O[i][j] *= alpha;
        }

        __syncthreads();   // everyone done reading K from KPs
        #pragma unroll
        for (int i = 0; i < 4; ++i)
            #pragma unroll
            for (int j = 0; j < 4; ++j)
                KPs[swz(n0 + j, m0 + i)] = S[i][j];
        __syncthreads();

        // O += P V  (64x64x64)
        #pragma unroll 16
        for (int d = 0; d < 64; ++d) {
            float4 a  = *(const float4*)&KPs[swz(d, m0)];
            float4 bv = *(const float4*)&Vs [d * 64 + n0];
            O[0][0] += a.x * bv.x; O[0][1] += a.x * bv.y; O[0][2] += a.x * bv.z; O[0][3] += a.x * bv.w;
            O[1][0] += a.y * bv.x; O[1][1] += a.y * bv.y; O[1][2] += a.y * bv.z; O[1][3] += a.y * bv.w;
            O[2][0] += a.z * bv.x; O[2][1] += a.z * bv.y; O[2][2] += a.z * bv.z; O[2][3] += a.z * bv.w;
            O[3][0] += a.w * bv.x; O[3][1] += a.w * bv.y; O[3][2] += a.w * bv.z; O[3][3] += a.w * bv.w;
        }
    }

    // epilogue: normalize, add value-residual, write [B*T, 512]
    #pragma unroll
    for (int i = 0; i < 4; ++i) {
        float invl = 1.0f / lI[i];
        size_t grow = ((size_t)b * Tt + qt * 64 + m0 + i) * 512 + h * 64 + n0;
        float4 vr = *(const float4*)(vres + grow);
        float4 o;
        o.x = O[i][0] * invl + vr.x;
        o.y = O[i][1] * invl + vr.y;
        o.z = O[i][2] * invl + vr.z;
        o.w = O[i][3] * invl + vr.w;
        *(float4*)(out + grow) = o;
    }
}

// ---------------------------------------------------------------------------
extern "C" void kernel_launch(void* const* d_in, const int* in_sizes, int n_in,
                              void* d_out, int out_size)
{
    const float* x    = (const float*)d_in[0];
    const float* WDQ  = (const float*)d_in[1];
    const float* WUQ  = (const float*)d_in[2];
    const float* WQR  = (const float*)d_in[3];
    const float* WDKV = (const float*)d_in[4];
    const float* WUK  = (const float*)d_in[5];
    const float* WUV  = (const float*)d_in[6];
    const float* WKR  = (const float*)d_in[7];
    const float* WVR  = (const float*)d_in[8];
    const float* WO   = (const float*)d_in[9];
    const float* qlnw = (const float*)d_in[10];
    const float* kvlnw= (const float*)d_in[11];
    const float* qhw  = (const float*)d_in[12];
    const float* khw  = (const float*)d_in[13];
    float* out = (float*)d_out;

    float *cq, *qn, *qr, *ckv, *kn, *kr, *vraw, *vres, *q, *k, *v, *ao;
    cudaGetSymbolAddress((void**)&cq,   g_cq);
    cudaGetSymbolAddress((void**)&qn,   g_qn);
    cudaGetSymbolAddress((void**)&qr,   g_qr);
    cudaGetSymbolAddress((void**)&ckv,  g_ckv);
    cudaGetSymbolAddress((void**)&kn,   g_kn);
    cudaGetSymbolAddress((void**)&kr,   g_kr);
    cudaGetSymbolAddress((void**)&vraw, g_vraw);
    cudaGetSymbolAddress((void**)&vres, g_vres);
    cudaGetSymbolAddress((void**)&q,    g_q);
    cudaGetSymbolAddress((void**)&k,    g_k);
    cudaGetSymbolAddress((void**)&v,    g_v);
    cudaGetSymbolAddress((void**)&ao,   g_ao);

    // Q path
    sgemm128<<<dim3(256/128, BT/128), 256>>>(x, WDQ, cq, BT, 256, 512);
    rms_inplace<<<BT, 128>>>(cq, qlnw, 256);
    sgemm128<<<dim3(2, 64), 256>>>(cq, WUQ, qn, BT, 256, 256);
    sgemm128<<<dim3(2, 64), 256>>>(cq, WQR, qr, BT, 256, 256);
    // KV path
    sgemm128<<<dim3(1, 64), 256>>>(x, WDKV, ckv, BT, 128, 512);
    rms_inplace<<<BT, 128>>>(ckv, kvlnw, 128);
    sgemm64<<<dim3(1, 128), 256>>>(ckv, WUK, kn, BT, 64, 128);
    sgemm128<<<dim3(1, 64), 256>>>(ckv, WUV, vraw, BT, 128, 128);
    sgemm64<<<dim3(1, 128), 256>>>(x, WKR, kr, BT, 64, 512);
    // value residual
    sgemm128<<<dim3(4, 64), 256>>>(x, WVR, vres, BT, 512, 512);
    // rope + head-norm + layout
    assemble<<<dim3(Tt, Bb), 256>>>(qn, qr, kn, kr, vraw, qhw, khw, q, k, v);
    // causal flash attention (+ residual add)
    flash64<<<dim3(Tt/64, Hh, Bb), 256>>>(q, k, v, vres, ao);
    // output projection
    sgemm128<<<dim3(4, 64), 256>>>(ao, WO, out, BT, 512, 512);
}